// round 9
// baseline (speedup 1.0000x reference)
#include <cuda_runtime.h>
#include <cuda_bf16.h>
#include <cstdint>

#define BB 64
#define SS 512
#define II 256
#define HH 512
#define CC 10

// ---------------- scratch ----------------
__device__ __nv_bfloat16 g_h0hi[(size_t)BB * SS * HH];
__device__ __nv_bfloat16 g_h0lo[(size_t)BB * SS * HH];
__device__ __nv_bfloat16 g_h1hi[(size_t)BB * SS * HH];
__device__ __nv_bfloat16 g_h1lo[(size_t)BB * SS * HH];
__device__ int g_flags[2 * 4 * 16];     // [layer][bg][jg] = steps completed

// ---------------- helpers ----------------
__device__ __forceinline__ uint32_t pk2(float e0, float e1) {
    uint32_t r; asm("cvt.rn.bf16x2.f32 %0, %1, %2;" : "=r"(r) : "f"(e1), "f"(e0)); return r;
}
__device__ __forceinline__ void split2(float2 v, uint32_t& h, uint32_t& l) {
    h = pk2(v.x, v.y);
    float f0 = __uint_as_float(h << 16);
    float f1 = __uint_as_float(h & 0xffff0000u);
    l = pk2(v.x - f0, v.y - f1);
}
__device__ __forceinline__ void split4(float4 v, uint32_t& h0, uint32_t& h1,
                                       uint32_t& l0, uint32_t& l1) {
    split2(make_float2(v.x, v.y), h0, l0);
    split2(make_float2(v.z, v.w), h1, l1);
}
__device__ __forceinline__ void mma16(float* d, const uint32_t* a, const uint32_t* b) {
    asm volatile("mma.sync.aligned.m16n8k16.row.col.f32.bf16.bf16.f32 "
                 "{%0,%1,%2,%3},{%4,%5,%6,%7},{%8,%9},{%0,%1,%2,%3};"
                 : "+f"(d[0]), "+f"(d[1]), "+f"(d[2]), "+f"(d[3])
                 : "r"(a[0]), "r"(a[1]), "r"(a[2]), "r"(a[3]), "r"(b[0]), "r"(b[1]));
}
__device__ __forceinline__ int ld_acq(const int* p) {
    int v; asm volatile("ld.acquire.gpu.global.s32 %0, [%1];" : "=r"(v) : "l"(p) : "memory");
    return v;
}
__device__ __forceinline__ void st_rel(int* p, int v) {
    asm volatile("st.release.gpu.global.s32 [%0], %1;" :: "l"(p), "r"(v) : "memory");
}
__device__ __forceinline__ void cpa16(void* smem, const void* g) {
    uint32_t s = (uint32_t)__cvta_generic_to_shared(smem);
    asm volatile("cp.async.cg.shared.global [%0], [%1], 16;" :: "r"(s), "l"(g) : "memory");
}
__device__ __forceinline__ void cpa_commit() {
    asm volatile("cp.async.commit_group;" ::: "memory");
}
template<int N> __device__ __forceinline__ void cpa_wait() {
    asm volatile("cp.async.wait_group %0;" :: "n"(N) : "memory");
}

// ---------------- fused 2-layer RNN + FC head ----------------
// 128 CTAs (1/SM): layer = bx>>6; inner 64 = 4 bg(16 batches) x 16 jg(32 j).
// 8 warps = 4 k-parts(128k) x 2 j-halves(16j). All W fragments in registers.
// cp.async staged exchange; ih-MMA overlaps h_prev flight; L1 prefetches input.
#define RP 260      // k-pair stride, 512-k stage (256 + 4)
#define XP 132      // k-pair stride, 256-k stage (128 + 4)
#define RDW 33      // reduce row stride
#define FSMEM_BYTES ((4 * 16 * RP + 64 * RDW) * 4)

__global__ __launch_bounds__(256, 1) void rnn_fused(
    const float* __restrict__ x,
    const float* __restrict__ w_ih0, const float* __restrict__ w_hh0,
    const float* __restrict__ b_ih0, const float* __restrict__ b_hh0,
    const float* __restrict__ w_ih1, const float* __restrict__ w_hh1,
    const float* __restrict__ b_ih1, const float* __restrict__ b_hh1,
    __nv_bfloat16* __restrict__ h0hi, __nv_bfloat16* __restrict__ h0lo,
    __nv_bfloat16* __restrict__ h1hi, __nv_bfloat16* __restrict__ h1lo,
    const float* __restrict__ w_fc, const float* __restrict__ b_fc,
    float* __restrict__ out,
    int* __restrict__ flags)
{
    extern __shared__ uint32_t smu[];
    uint32_t* Php = smu;                 // h_prev hi [16][RP]
    uint32_t* Plp = smu + 16 * RP;       // h_prev lo
    uint32_t* Ihp = smu + 2 * 16 * RP;   // input hi  [16][RP or XP]
    uint32_t* Ilp = smu + 3 * 16 * RP;   // input lo
    float*    Rd  = (float*)(smu + 4 * 16 * RP);  // [4*16][RDW]
    __shared__ int s_pf;

    const int tid = threadIdx.x, lane = tid & 31, wp = tid >> 5;
    const int gid = lane >> 2, tg = lane & 3;
    const int wk = wp & 3, wj = wp >> 2;
    const int layer = blockIdx.x >> 6;
    const int inner = blockIdx.x & 63;
    const int bg = inner & 3, jg = inner >> 2;
    const int b0 = bg * 16, jbase = jg * 32;
    const int rb = tid >> 4, rjp = tid & 15;
    const bool L1 = (layer == 1);

    const float* whh = L1 ? w_hh1 : w_hh0;
    const float* wih = L1 ? w_ih1 : w_ih0;
    const float* bi  = L1 ? b_ih1 : b_ih0;
    const float* bh  = L1 ? b_hh1 : b_hh0;
    uint32_t* Ohw = (uint32_t*)(L1 ? h1hi : h0hi);
    uint32_t* Olw = (uint32_t*)(L1 ? h1lo : h0lo);
    const uint32_t* ihg = (const uint32_t*)h0hi;
    const uint32_t* ilg = (const uint32_t*)h0lo;
    int* fown_arr = flags + layer * 64 + bg * 16;
    int* fdep_arr = flags + bg * 16;
    int* myflag   = fown_arr + jg;

    const float bias0 = bi[jbase + 2 * rjp]     + bh[jbase + 2 * rjp];
    const float bias1 = bi[jbase + 2 * rjp + 1] + bh[jbase + 2 * rjp + 1];

    // ---- W_hh fragments -> registers ----
    uint32_t whf[8][2][2], wlf[8][2][2];
#pragma unroll
    for (int kc = 0; kc < 8; kc++) {
        int kp = wk * 64 + kc * 8 + tg;
#pragma unroll
        for (int nt = 0; nt < 2; nt++) {
            const float* wr = whh + (size_t)(jbase + wj * 16 + nt * 8 + gid) * HH;
            split2(*(const float2*)(wr + 2 * kp),     whf[kc][nt][0], wlf[kc][nt][0]);
            split2(*(const float2*)(wr + 2 * kp + 8), whf[kc][nt][1], wlf[kc][nt][1]);
        }
    }
    // ---- W_ih fragments ----
    uint32_t uhf[8][2][2], ulf[8][2][2];
    if (L1) {
#pragma unroll
        for (int kc = 0; kc < 8; kc++) {
            int kp = wk * 64 + kc * 8 + tg;
#pragma unroll
            for (int nt = 0; nt < 2; nt++) {
                const float* wr = wih + (size_t)(jbase + wj * 16 + nt * 8 + gid) * HH;
                split2(*(const float2*)(wr + 2 * kp),     uhf[kc][nt][0], ulf[kc][nt][0]);
                split2(*(const float2*)(wr + 2 * kp + 8), uhf[kc][nt][1], ulf[kc][nt][1]);
            }
        }
    } else {
#pragma unroll
        for (int kc = 0; kc < 4; kc++) {
            int kp = wk * 32 + kc * 8 + tg;
#pragma unroll
            for (int nt = 0; nt < 2; nt++) {
                const float* wr = wih + (size_t)(jbase + wj * 16 + nt * 8 + gid) * II;
                split2(*(const float2*)(wr + 2 * kp),     uhf[kc][nt][0], ulf[kc][nt][0]);
                split2(*(const float2*)(wr + 2 * kp + 8), uhf[kc][nt][1], ulf[kc][nt][1]);
            }
        }
    }

    if (tid == 0) s_pf = 0;

    // ---- L0 prologue: stage x_0 ----
    if (!L1) {
#pragma unroll
        for (int i = 0; i < 4; i++) {
            int f = tid + i * 256;
            int b = f >> 6, q = f & 63;
            float4 v = *(const float4*)(x + ((size_t)(b0 + b) * SS) * II + q * 4);
            uint32_t h0v, h1v, l0v, l1v; split4(v, h0v, h1v, l0v, l1v);
            *(uint2*)&Ihp[b * XP + q * 2] = make_uint2(h0v, h1v);
            *(uint2*)&Ilp[b * XP + q * 2] = make_uint2(l0v, l1v);
        }
    }
    __syncthreads();

    cpa_commit();                       // pre-loop empty group: invariant = 1 outstanding
    int pf = 0;

    for (int t = 0; t < SS; t++) {
        // ---- poll (warp 0, parallel lanes) ----
        if (wp == 0) {
            if (L1) {
                if (lane < 16) { while (ld_acq(fown_arr + lane) < t) { } }
                else if (!pf)  { while (ld_acq(fdep_arr + lane - 16) < t + 1) { } }
            } else if (t > 0 && lane < 16) {
                while (ld_acq(fown_arr + lane) < t) { }
            }
        }
        __syncthreads();

        // ---- group A: input (L1 slow path only) ----
        if (L1 && !pf) {
#pragma unroll
            for (int i = 0; i < 4; i++) {
                int f = tid + i * 256;
                int b = f >> 6, q = f & 63;
                size_t off = ((size_t)(b0 + b) * SS + t) * (HH / 2) + q * 4;
                cpa16(&Ihp[b * RP + q * 4], ihg + off);
                cpa16(&Ilp[b * RP + q * 4], ilg + off);
            }
        }
        cpa_commit();
        // ---- group B: h_prev ----
        if (t > 0) {
#pragma unroll
            for (int i = 0; i < 4; i++) {
                int f = tid + i * 256;
                int b = f >> 6, q = f & 63;
                size_t off = ((size_t)(b0 + b) * SS + (t - 1)) * (HH / 2) + q * 4;
                cpa16(&Php[b * RP + q * 4], Ohw + off);
                cpa16(&Plp[b * RP + q * 4], Olw + off);
            }
        } else {
#pragma unroll
            for (int i = 0; i < 4; i++) {
                int f = tid + i * 256;
                int b = f >> 6, q = f & 63;
                uint4 z = make_uint4(0, 0, 0, 0);
                *(uint4*)&Php[b * RP + q * 4] = z;
                *(uint4*)&Plp[b * RP + q * 4] = z;
            }
        }
        cpa_commit();

        cpa_wait<1>();                  // input (and older) complete; h_prev may fly
        __syncthreads();

        float acc[2][4];
#pragma unroll
        for (int nt = 0; nt < 2; nt++)
#pragma unroll
            for (int c = 0; c < 4; c++) acc[nt][c] = 0.f;

        // ---- input @ W_ih (h_prev cp.async in flight) ----
        if (L1) {
#pragma unroll
            for (int kc = 0; kc < 8; kc++) {
                int kp = wk * 64 + kc * 8 + tg;
                int o0 = gid * RP + kp, o1 = (gid + 8) * RP + kp;
                uint32_t ahi[4] = { Ihp[o0], Ihp[o1], Ihp[o0 + 4], Ihp[o1 + 4] };
                uint32_t alo[4] = { Ilp[o0], Ilp[o1], Ilp[o0 + 4], Ilp[o1 + 4] };
#pragma unroll
                for (int nt = 0; nt < 2; nt++) {
                    mma16(acc[nt], ahi, uhf[kc][nt]);
                    mma16(acc[nt], ahi, ulf[kc][nt]);
                    mma16(acc[nt], alo, uhf[kc][nt]);
                }
            }
        } else {
#pragma unroll
            for (int kc = 0; kc < 4; kc++) {
                int kp = wk * 32 + kc * 8 + tg;
                int o0 = gid * XP + kp, o1 = (gid + 8) * XP + kp;
                uint32_t ahi[4] = { Ihp[o0], Ihp[o1], Ihp[o0 + 4], Ihp[o1 + 4] };
                uint32_t alo[4] = { Ilp[o0], Ilp[o1], Ilp[o0 + 4], Ilp[o1 + 4] };
#pragma unroll
                for (int nt = 0; nt < 2; nt++) {
                    mma16(acc[nt], ahi, uhf[kc][nt]);
                    mma16(acc[nt], ahi, ulf[kc][nt]);
                    mma16(acc[nt], alo, uhf[kc][nt]);
                }
            }
        }

        cpa_wait<0>();                  // h_prev ready
        __syncthreads();

        // ---- L0: issue x_{t+1} loads (latency hidden under hh MMA) ----
        float4 xv[4];
        if (!L1 && t + 1 < SS) {
#pragma unroll
            for (int i = 0; i < 4; i++) {
                int f = tid + i * 256;
                int b = f >> 6, q = f & 63;
                xv[i] = *(const float4*)(x + ((size_t)(b0 + b) * SS + (t + 1)) * II + q * 4);
            }
        }

        // ---- h_prev @ W_hh ----
#pragma unroll
        for (int kc = 0; kc < 8; kc++) {
            int kp = wk * 64 + kc * 8 + tg;
            int o0 = gid * RP + kp, o1 = (gid + 8) * RP + kp;
            uint32_t ahi[4] = { Php[o0], Php[o1], Php[o0 + 4], Php[o1 + 4] };
            uint32_t alo[4] = { Plp[o0], Plp[o1], Plp[o0 + 4], Plp[o1 + 4] };
#pragma unroll
            for (int nt = 0; nt < 2; nt++) {
                mma16(acc[nt], ahi, whf[kc][nt]);
                mma16(acc[nt], ahi, wlf[kc][nt]);
                mma16(acc[nt], alo, whf[kc][nt]);
            }
        }

        // ---- L0: split + STS x_{t+1} (Ihp free after ih MMA) ----
        if (!L1 && t + 1 < SS) {
#pragma unroll
            for (int i = 0; i < 4; i++) {
                int f = tid + i * 256;
                int b = f >> 6, q = f & 63;
                uint32_t h0v, h1v, l0v, l1v; split4(xv[i], h0v, h1v, l0v, l1v);
                *(uint2*)&Ihp[b * XP + q * 2] = make_uint2(h0v, h1v);
                *(uint2*)&Ilp[b * XP + q * 2] = make_uint2(l0v, l1v);
            }
        }

        // ---- L1: one-shot prefetch decision for t+1 ----
        if (L1 && wp == 0) {
            bool c = (lane < 16) ? (ld_acq(fdep_arr + lane) >= t + 2) : true;
            unsigned m = __ballot_sync(0xffffffffu, c);
            if (lane == 0) s_pf = (m == 0xffffffffu) ? 1 : 0;
        }

        // ---- partials -> Rd ----
#pragma unroll
        for (int nt = 0; nt < 2; nt++) {
            int col = wj * 16 + nt * 8 + tg * 2;
            int r0 = (wk * 16 + gid) * RDW + col;
            int r1 = (wk * 16 + gid + 8) * RDW + col;
            Rd[r0] = acc[nt][0]; Rd[r0 + 1] = acc[nt][1];
            Rd[r1] = acc[nt][2]; Rd[r1 + 1] = acc[nt][3];
        }
        __syncthreads();

        // ---- reduce, tanh, split-pack-store ----
        {
            float s0 = 0.f, s1 = 0.f;
#pragma unroll
            for (int r = 0; r < 4; r++) {
                int o = (r * 16 + rb) * RDW + 2 * rjp;
                s0 += Rd[o]; s1 += Rd[o + 1];
            }
            float v0 = tanhf(bias0 + s0);
            float v1 = tanhf(bias1 + s1);
            uint32_t hp, lp; split2(make_float2(v0, v1), hp, lp);
            size_t oo = ((size_t)(b0 + rb) * SS + t) * (HH / 2) + (jbase >> 1) + rjp;
            Ohw[oo] = hp;
            Olw[oo] = lp;
        }
        __syncthreads();
        if (tid == 0) st_rel(myflag, t + 1);

        // ---- group C: prefetch input t+1 (L1 fast path) ----
        int newpf = 0;
        if (L1 && t + 1 < SS) {
            newpf = s_pf;
            if (newpf) {
#pragma unroll
                for (int i = 0; i < 4; i++) {
                    int f = tid + i * 256;
                    int b = f >> 6, q = f & 63;
                    size_t off = ((size_t)(b0 + b) * SS + (t + 1)) * (HH / 2) + q * 4;
                    cpa16(&Ihp[b * RP + q * 4], ihg + off);
                    cpa16(&Ilp[b * RP + q * 4], ilg + off);
                }
            }
        }
        cpa_commit();
        pf = newpf;
    }
    cpa_wait<0>();

    // ---- FC head: L0 CTAs (idle now), one per batch ----
    if (!L1 && inner < BB) {
        const int b = inner;
        if (wp == 0 && lane < 16) {
            const int* f1 = flags + 64 + (b >> 4) * 16 + lane;
            while (ld_acq(f1) < SS) { }
        }
        __syncthreads();
        const __nv_bfloat16* hb = h1hi + ((size_t)b * SS + (SS - 1)) * HH;
        const __nv_bfloat16* lb = h1lo + ((size_t)b * SS + (SS - 1)) * HH;
        for (int c = wp; c < CC; c += 8) {
            float acc = 0.f;
            for (int j = lane; j < HH; j += 32) {
                float h = __bfloat162float(hb[j]) + __bfloat162float(lb[j]);
                acc += h * w_fc[c * HH + j];
            }
#pragma unroll
            for (int o = 16; o; o >>= 1) acc += __shfl_down_sync(0xffffffffu, acc, o);
            if (lane == 0) out[b * CC + c] = acc + b_fc[c];
        }
    }
}

// ---------------- launch ----------------
extern "C" void kernel_launch(void* const* d_in, const int* in_sizes, int n_in,
                              void* d_out, int out_size)
{
    const float* x     = (const float*)d_in[0];
    const float* w_ih0 = (const float*)d_in[1];
    const float* w_hh0 = (const float*)d_in[2];
    const float* b_ih0 = (const float*)d_in[3];
    const float* b_hh0 = (const float*)d_in[4];
    const float* w_ih1 = (const float*)d_in[5];
    const float* w_hh1 = (const float*)d_in[6];
    const float* b_ih1 = (const float*)d_in[7];
    const float* b_hh1 = (const float*)d_in[8];
    const float* w_fc  = (const float*)d_in[9];
    const float* b_fc  = (const float*)d_in[10];
    float* out = (float*)d_out;

    __nv_bfloat16 *h0hi, *h0lo, *h1hi, *h1lo;
    int* flags;
    cudaGetSymbolAddress((void**)&h0hi, g_h0hi);
    cudaGetSymbolAddress((void**)&h0lo, g_h0lo);
    cudaGetSymbolAddress((void**)&h1hi, g_h1hi);
    cudaGetSymbolAddress((void**)&h1lo, g_h1lo);
    cudaGetSymbolAddress((void**)&flags, g_flags);

    cudaFuncSetAttribute(rnn_fused,
                         cudaFuncAttributeMaxDynamicSharedMemorySize, FSMEM_BYTES);

    cudaMemsetAsync(flags, 0, 2 * 4 * 16 * sizeof(int));

    rnn_fused<<<128, 256, FSMEM_BYTES>>>(x,
                                         w_ih0, w_hh0, b_ih0, b_hh0,
                                         w_ih1, w_hh1, b_ih1, b_hh1,
                                         h0hi, h0lo, h1hi, h1lo,
                                         w_fc, b_fc, out, flags);
}

// round 10
// speedup vs baseline: 1.1995x; 1.1995x over previous
#include <cuda_runtime.h>
#include <cuda_bf16.h>
#include <cstdint>

#define BB 64
#define SS 512
#define II 256
#define HH 512
#define CC 10

// ---------------- scratch ----------------
__device__ __nv_bfloat16 g_h0hi[(size_t)BB * SS * HH];
__device__ __nv_bfloat16 g_h0lo[(size_t)BB * SS * HH];
__device__ __nv_bfloat16 g_h1hi[(size_t)BB * SS * HH];
__device__ __nv_bfloat16 g_h1lo[(size_t)BB * SS * HH];
__device__ int g_flags[2 * 4 * 16];     // [layer][bg][jg] = steps completed

// ---------------- helpers ----------------
__device__ __forceinline__ uint32_t pk2(float e0, float e1) {
    uint32_t r; asm("cvt.rn.bf16x2.f32 %0, %1, %2;" : "=r"(r) : "f"(e1), "f"(e0)); return r;
}
__device__ __forceinline__ void split2(float2 v, uint32_t& h, uint32_t& l) {
    h = pk2(v.x, v.y);
    float f0 = __uint_as_float(h << 16);
    float f1 = __uint_as_float(h & 0xffff0000u);
    l = pk2(v.x - f0, v.y - f1);
}
__device__ __forceinline__ void split4(float4 v, uint32_t& h0, uint32_t& h1,
                                       uint32_t& l0, uint32_t& l1) {
    split2(make_float2(v.x, v.y), h0, l0);
    split2(make_float2(v.z, v.w), h1, l1);
}
__device__ __forceinline__ void mma16(float* d, const uint32_t* a, const uint32_t* b) {
    asm volatile("mma.sync.aligned.m16n8k16.row.col.f32.bf16.bf16.f32 "
                 "{%0,%1,%2,%3},{%4,%5,%6,%7},{%8,%9},{%0,%1,%2,%3};"
                 : "+f"(d[0]), "+f"(d[1]), "+f"(d[2]), "+f"(d[3])
                 : "r"(a[0]), "r"(a[1]), "r"(a[2]), "r"(a[3]), "r"(b[0]), "r"(b[1]));
}
__device__ __forceinline__ int ld_acq(const int* p) {
    int v; asm volatile("ld.acquire.gpu.global.s32 %0, [%1];" : "=r"(v) : "l"(p) : "memory");
    return v;
}
__device__ __forceinline__ void st_rel(int* p, int v) {
    asm volatile("st.release.gpu.global.s32 [%0], %1;" :: "l"(p), "r"(v) : "memory");
}

// ---------------- fused 2-layer RNN + FC head ----------------
// 128 CTAs (1/SM): layer = bx>>6; inner 64 = 4 bg(16 batches) x 16 jg(32 j).
// 8 warps = 4 k-parts(128k) x 2 j-halves(16j). All W fragments in registers.
// Deferred-input pipeline: ih-MMA for step t+1 runs AFTER signaling step t,
// so the critical chain carries only stage(h_prev) + hh-MMA + reduce.
#define RP 260      // k-pair stride, 512-k stage (256 + 4)
#define XP 132      // k-pair stride, 256-k stage (128 + 4)
#define RDW 33      // reduce row stride
#define FSMEM_BYTES ((4 * 16 * RP + 64 * RDW) * 4)

__global__ __launch_bounds__(256, 1) void rnn_fused(
    const float* __restrict__ x,
    const float* __restrict__ w_ih0, const float* __restrict__ w_hh0,
    const float* __restrict__ b_ih0, const float* __restrict__ b_hh0,
    const float* __restrict__ w_ih1, const float* __restrict__ w_hh1,
    const float* __restrict__ b_ih1, const float* __restrict__ b_hh1,
    __nv_bfloat16* __restrict__ h0hi, __nv_bfloat16* __restrict__ h0lo,
    __nv_bfloat16* __restrict__ h1hi, __nv_bfloat16* __restrict__ h1lo,
    const float* __restrict__ w_fc, const float* __restrict__ b_fc,
    float* __restrict__ out,
    int* __restrict__ flags)
{
    extern __shared__ uint32_t smu[];
    uint32_t* Php = smu;                 // h_prev hi [16][RP]
    uint32_t* Plp = smu + 16 * RP;       // h_prev lo
    uint32_t* Ihp = smu + 2 * 16 * RP;   // input hi  [16][RP or XP]
    uint32_t* Ilp = smu + 3 * 16 * RP;   // input lo
    float*    Rd  = (float*)(smu + 4 * 16 * RP);  // [4*16][RDW]

    const int tid = threadIdx.x, lane = tid & 31, wp = tid >> 5;
    const int gid = lane >> 2, tg = lane & 3;
    const int wk = wp & 3, wj = wp >> 2;
    const int layer = blockIdx.x >> 6;
    const int inner = blockIdx.x & 63;
    const int bg = inner & 3, jg = inner >> 2;
    const int b0 = bg * 16, jbase = jg * 32;
    const int rb = tid >> 4, rjp = tid & 15;
    const bool L1 = (layer == 1);

    const float* whh = L1 ? w_hh1 : w_hh0;
    const float* wih = L1 ? w_ih1 : w_ih0;
    const float* bi  = L1 ? b_ih1 : b_ih0;
    const float* bh  = L1 ? b_hh1 : b_hh0;
    uint32_t* Ohw = (uint32_t*)(L1 ? h1hi : h0hi);
    uint32_t* Olw = (uint32_t*)(L1 ? h1lo : h0lo);
    const uint32_t* ihg = (const uint32_t*)h0hi;
    const uint32_t* ilg = (const uint32_t*)h0lo;
    int* fown_arr = flags + layer * 64 + bg * 16;
    int* fdep_arr = flags + bg * 16;
    int* myflag   = fown_arr + jg;

    const float bias0 = bi[jbase + 2 * rjp]     + bh[jbase + 2 * rjp];
    const float bias1 = bi[jbase + 2 * rjp + 1] + bh[jbase + 2 * rjp + 1];

    // ---- W_hh fragments -> registers ----
    uint32_t whf[8][2][2], wlf[8][2][2];
#pragma unroll
    for (int kc = 0; kc < 8; kc++) {
        int kp = wk * 64 + kc * 8 + tg;
#pragma unroll
        for (int nt = 0; nt < 2; nt++) {
            const float* wr = whh + (size_t)(jbase + wj * 16 + nt * 8 + gid) * HH;
            split2(*(const float2*)(wr + 2 * kp),     whf[kc][nt][0], wlf[kc][nt][0]);
            split2(*(const float2*)(wr + 2 * kp + 8), whf[kc][nt][1], wlf[kc][nt][1]);
        }
    }
    // ---- W_ih fragments ----
    uint32_t uhf[8][2][2], ulf[8][2][2];
    if (L1) {
#pragma unroll
        for (int kc = 0; kc < 8; kc++) {
            int kp = wk * 64 + kc * 8 + tg;
#pragma unroll
            for (int nt = 0; nt < 2; nt++) {
                const float* wr = wih + (size_t)(jbase + wj * 16 + nt * 8 + gid) * HH;
                split2(*(const float2*)(wr + 2 * kp),     uhf[kc][nt][0], ulf[kc][nt][0]);
                split2(*(const float2*)(wr + 2 * kp + 8), uhf[kc][nt][1], ulf[kc][nt][1]);
            }
        }
    } else {
#pragma unroll
        for (int kc = 0; kc < 4; kc++) {
            int kp = wk * 32 + kc * 8 + tg;
#pragma unroll
            for (int nt = 0; nt < 2; nt++) {
                const float* wr = wih + (size_t)(jbase + wj * 16 + nt * 8 + gid) * II;
                split2(*(const float2*)(wr + 2 * kp),     uhf[kc][nt][0], ulf[kc][nt][0]);
                split2(*(const float2*)(wr + 2 * kp + 8), uhf[kc][nt][1], ulf[kc][nt][1]);
            }
        }
    }

    float acc[2][4];

    auto ih_mma = [&]() {
        if (L1) {
#pragma unroll
            for (int kc = 0; kc < 8; kc++) {
                int kp = wk * 64 + kc * 8 + tg;
                int o0 = gid * RP + kp, o1 = (gid + 8) * RP + kp;
                uint32_t ahi[4] = { Ihp[o0], Ihp[o1], Ihp[o0 + 4], Ihp[o1 + 4] };
                uint32_t alo[4] = { Ilp[o0], Ilp[o1], Ilp[o0 + 4], Ilp[o1 + 4] };
#pragma unroll
                for (int nt = 0; nt < 2; nt++) {
                    mma16(acc[nt], ahi, uhf[kc][nt]);
                    mma16(acc[nt], ahi, ulf[kc][nt]);
                    mma16(acc[nt], alo, uhf[kc][nt]);
                }
            }
        } else {
#pragma unroll
            for (int kc = 0; kc < 4; kc++) {
                int kp = wk * 32 + kc * 8 + tg;
                int o0 = gid * XP + kp, o1 = (gid + 8) * XP + kp;
                uint32_t ahi[4] = { Ihp[o0], Ihp[o1], Ihp[o0 + 4], Ihp[o1 + 4] };
                uint32_t alo[4] = { Ilp[o0], Ilp[o1], Ilp[o0 + 4], Ilp[o1 + 4] };
#pragma unroll
                for (int nt = 0; nt < 2; nt++) {
                    mma16(acc[nt], ahi, uhf[kc][nt]);
                    mma16(acc[nt], ahi, ulf[kc][nt]);
                    mma16(acc[nt], alo, uhf[kc][nt]);
                }
            }
        }
    };

    // ---- prologue: stage input(0), ih-MMA(0) ----
    if (L1) {
        if (wp == 0 && lane < 16) { while (ld_acq(fdep_arr + lane) < 1) { } }
        __syncthreads();
#pragma unroll
        for (int i = 0; i < 4; i++) {
            int f = tid + i * 256;
            int b = f >> 6, q = f & 63;
            size_t off = ((size_t)(b0 + b) * SS) * (HH / 2) + q * 4;
            *(uint4*)&Ihp[b * RP + q * 4] = __ldcg((const uint4*)(ihg + off));
            *(uint4*)&Ilp[b * RP + q * 4] = __ldcg((const uint4*)(ilg + off));
        }
    } else {
#pragma unroll
        for (int i = 0; i < 4; i++) {
            int f = tid + i * 256;
            int b = f >> 6, q = f & 63;
            float4 v = *(const float4*)(x + ((size_t)(b0 + b) * SS) * II + q * 4);
            uint32_t h0v, h1v, l0v, l1v; split4(v, h0v, h1v, l0v, l1v);
            *(uint2*)&Ihp[b * XP + q * 2] = make_uint2(h0v, h1v);
            *(uint2*)&Ilp[b * XP + q * 2] = make_uint2(l0v, l1v);
        }
    }
    __syncthreads();
#pragma unroll
    for (int nt = 0; nt < 2; nt++)
#pragma unroll
        for (int c = 0; c < 4; c++) acc[nt][c] = 0.f;
    ih_mma();

    for (int t = 0; t < SS; t++) {
        // ---- L0: issue next x loads early (latency spans whole iteration) ----
        float4 xv[4];
        if (!L1 && t + 1 < SS) {
#pragma unroll
            for (int i = 0; i < 4; i++) {
                int f = tid + i * 256;
                int b = f >> 6, q = f & 63;
                xv[i] = *(const float4*)(x + ((size_t)(b0 + b) * SS + (t + 1)) * II + q * 4);
            }
        }

        // ---- head: poll own producers (h_{t-1}) ----
        if (t > 0) {
            if (wp == 0 && lane < 16) { while (ld_acq(fown_arr + lane) < t) { } }
            __syncthreads();
#pragma unroll
            for (int i = 0; i < 4; i++) {
                int f = tid + i * 256;
                int b = f >> 6, q = f & 63;
                size_t off = ((size_t)(b0 + b) * SS + (t - 1)) * (HH / 2) + q * 4;
                *(uint4*)&Php[b * RP + q * 4] = __ldcg((const uint4*)(Ohw + off));
                *(uint4*)&Plp[b * RP + q * 4] = __ldcg((const uint4*)(Olw + off));
            }
            __syncthreads();

            // ---- h_prev @ W_hh (into acc, which holds ih(t)) ----
#pragma unroll
            for (int kc = 0; kc < 8; kc++) {
                int kp = wk * 64 + kc * 8 + tg;
                int o0 = gid * RP + kp, o1 = (gid + 8) * RP + kp;
                uint32_t ahi[4] = { Php[o0], Php[o1], Php[o0 + 4], Php[o1 + 4] };
                uint32_t alo[4] = { Plp[o0], Plp[o1], Plp[o0 + 4], Plp[o1 + 4] };
#pragma unroll
                for (int nt = 0; nt < 2; nt++) {
                    mma16(acc[nt], ahi, whf[kc][nt]);
                    mma16(acc[nt], ahi, wlf[kc][nt]);
                    mma16(acc[nt], alo, whf[kc][nt]);
                }
            }
        }
        // (t == 0: h_prev = 0, acc already holds ih(0))

        // ---- partials -> Rd ----
#pragma unroll
        for (int nt = 0; nt < 2; nt++) {
            int col = wj * 16 + nt * 8 + tg * 2;
            int r0 = (wk * 16 + gid) * RDW + col;
            int r1 = (wk * 16 + gid + 8) * RDW + col;
            Rd[r0] = acc[nt][0]; Rd[r0 + 1] = acc[nt][1];
            Rd[r1] = acc[nt][2]; Rd[r1 + 1] = acc[nt][3];
        }
        __syncthreads();

        // ---- reduce, tanh, split-pack-store ----
        {
            float s0 = 0.f, s1 = 0.f;
#pragma unroll
            for (int r = 0; r < 4; r++) {
                int o = (r * 16 + rb) * RDW + 2 * rjp;
                s0 += Rd[o]; s1 += Rd[o + 1];
            }
            float v0 = tanhf(bias0 + s0);
            float v1 = tanhf(bias1 + s1);
            uint32_t hp, lp; split2(make_float2(v0, v1), hp, lp);
            size_t oo = ((size_t)(b0 + rb) * SS + t) * (HH / 2) + (jbase >> 1) + rjp;
            Ohw[oo] = hp;
            Olw[oo] = lp;
        }
        __syncthreads();
        if (tid == 0) st_rel(myflag, t + 1);

        // ---- tail (slack window): stage input(t+1), ih-MMA(t+1) ----
        if (t + 1 < SS) {
            if (L1) {
                if (wp == 0 && lane < 16) { while (ld_acq(fdep_arr + lane) < t + 2) { } }
                __syncthreads();
#pragma unroll
                for (int i = 0; i < 4; i++) {
                    int f = tid + i * 256;
                    int b = f >> 6, q = f & 63;
                    size_t off = ((size_t)(b0 + b) * SS + (t + 1)) * (HH / 2) + q * 4;
                    *(uint4*)&Ihp[b * RP + q * 4] = __ldcg((const uint4*)(ihg + off));
                    *(uint4*)&Ilp[b * RP + q * 4] = __ldcg((const uint4*)(ilg + off));
                }
            } else {
#pragma unroll
                for (int i = 0; i < 4; i++) {
                    int f = tid + i * 256;
                    int b = f >> 6, q = f & 63;
                    uint32_t h0v, h1v, l0v, l1v; split4(xv[i], h0v, h1v, l0v, l1v);
                    *(uint2*)&Ihp[b * XP + q * 2] = make_uint2(h0v, h1v);
                    *(uint2*)&Ilp[b * XP + q * 2] = make_uint2(l0v, l1v);
                }
            }
            __syncthreads();
#pragma unroll
            for (int nt = 0; nt < 2; nt++)
#pragma unroll
                for (int c = 0; c < 4; c++) acc[nt][c] = 0.f;
            ih_mma();
        }
    }

    // ---- FC head: L0 CTAs (idle now), one per batch ----
    if (!L1 && inner < BB) {
        const int b = inner;
        if (wp == 0 && lane < 16) {
            const int* f1 = flags + 64 + (b >> 4) * 16 + lane;
            while (ld_acq(f1) < SS) { }
        }
        __syncthreads();
        const __nv_bfloat16* hb = h1hi + ((size_t)b * SS + (SS - 1)) * HH;
        const __nv_bfloat16* lb = h1lo + ((size_t)b * SS + (SS - 1)) * HH;
        for (int c = wp; c < CC; c += 8) {
            float accf = 0.f;
            for (int j = lane; j < HH; j += 32) {
                float h = __bfloat162float(hb[j]) + __bfloat162float(lb[j]);
                accf += h * w_fc[c * HH + j];
            }
#pragma unroll
            for (int o = 16; o; o >>= 1) accf += __shfl_down_sync(0xffffffffu, accf, o);
            if (lane == 0) out[b * CC + c] = accf + b_fc[c];
        }
    }
}

// ---------------- launch ----------------
extern "C" void kernel_launch(void* const* d_in, const int* in_sizes, int n_in,
                              void* d_out, int out_size)
{
    const float* x     = (const float*)d_in[0];
    const float* w_ih0 = (const float*)d_in[1];
    const float* w_hh0 = (const float*)d_in[2];
    const float* b_ih0 = (const float*)d_in[3];
    const float* b_hh0 = (const float*)d_in[4];
    const float* w_ih1 = (const float*)d_in[5];
    const float* w_hh1 = (const float*)d_in[6];
    const float* b_ih1 = (const float*)d_in[7];
    const float* b_hh1 = (const float*)d_in[8];
    const float* w_fc  = (const float*)d_in[9];
    const float* b_fc  = (const float*)d_in[10];
    float* out = (float*)d_out;

    __nv_bfloat16 *h0hi, *h0lo, *h1hi, *h1lo;
    int* flags;
    cudaGetSymbolAddress((void**)&h0hi, g_h0hi);
    cudaGetSymbolAddress((void**)&h0lo, g_h0lo);
    cudaGetSymbolAddress((void**)&h1hi, g_h1hi);
    cudaGetSymbolAddress((void**)&h1lo, g_h1lo);
    cudaGetSymbolAddress((void**)&flags, g_flags);

    cudaFuncSetAttribute(rnn_fused,
                         cudaFuncAttributeMaxDynamicSharedMemorySize, FSMEM_BYTES);

    cudaMemsetAsync(flags, 0, 2 * 4 * 16 * sizeof(int));

    rnn_fused<<<128, 256, FSMEM_BYTES>>>(x,
                                         w_ih0, w_hh0, b_ih0, b_hh0,
                                         w_ih1, w_hh1, b_ih1, b_hh1,
                                         h0hi, h0lo, h1hi, h1lo,
                                         w_fc, b_fc, out, flags);
}

// round 11
// speedup vs baseline: 1.2241x; 1.0205x over previous
#include <cuda_runtime.h>
#include <cuda_bf16.h>
#include <cstdint>

#define BB 64
#define SS 512
#define II 256
#define HH 512
#define CC 10
#define FS 32            // flag stride in ints (128B line per counter)

// ---------------- scratch ----------------
// blocked h storage: [t][bg(4)][jg(16)] -> block of 256 u32 (16 b x 16 kp)
__device__ uint32_t g_h0hi_b[(size_t)SS * 64 * 256];
__device__ uint32_t g_h0lo_b[(size_t)SS * 64 * 256];
__device__ uint32_t g_h1hi_b[(size_t)SS * 64 * 256];
__device__ uint32_t g_h1lo_b[(size_t)SS * 64 * 256];
__device__ int g_flags[2 * 4 * SS * FS];   // counter per (layer,bg,t), padded

__device__ __forceinline__ size_t fidx(int layer, int bg, int t) {
    return ((size_t)(layer * 4 + bg) * SS + t) * FS;
}

// ---------------- helpers ----------------
__device__ __forceinline__ uint32_t pk2(float e0, float e1) {
    uint32_t r; asm("cvt.rn.bf16x2.f32 %0, %1, %2;" : "=r"(r) : "f"(e1), "f"(e0)); return r;
}
__device__ __forceinline__ void split2(float2 v, uint32_t& h, uint32_t& l) {
    h = pk2(v.x, v.y);
    float f0 = __uint_as_float(h << 16);
    float f1 = __uint_as_float(h & 0xffff0000u);
    l = pk2(v.x - f0, v.y - f1);
}
__device__ __forceinline__ void split4(float4 v, uint32_t& h0, uint32_t& h1,
                                       uint32_t& l0, uint32_t& l1) {
    split2(make_float2(v.x, v.y), h0, l0);
    split2(make_float2(v.z, v.w), h1, l1);
}
__device__ __forceinline__ void mma16(float* d, const uint32_t* a, const uint32_t* b) {
    asm volatile("mma.sync.aligned.m16n8k16.row.col.f32.bf16.bf16.f32 "
                 "{%0,%1,%2,%3},{%4,%5,%6,%7},{%8,%9},{%0,%1,%2,%3};"
                 : "+f"(d[0]), "+f"(d[1]), "+f"(d[2]), "+f"(d[3])
                 : "r"(a[0]), "r"(a[1]), "r"(a[2]), "r"(a[3]), "r"(b[0]), "r"(b[1]));
}
__device__ __forceinline__ int ld_acq(const int* p) {
    int v; asm volatile("ld.acquire.gpu.global.s32 %0, [%1];" : "=r"(v) : "l"(p) : "memory");
    return v;
}
__device__ __forceinline__ void red_rel(int* p, int v) {
    asm volatile("red.release.gpu.global.add.s32 [%0], %1;" :: "l"(p), "r"(v) : "memory");
}

// ---------------- fused 2-layer RNN + FC head ----------------
// 128 CTAs (1/SM): layer = bx>>6; inner 64 = 4 bg(16 batches) x 16 jg(32 j).
// 8 warps = 4 k-parts(128k) x 2 j-halves(16j). All W fragments in registers.
#define RP 260      // k-pair stride, 512-k stage (256 + 4)
#define XP 132      // k-pair stride, 256-k stage (128 + 4)
#define RDW 33      // reduce row stride
#define FSMEM_BYTES ((4 * 16 * RP + 64 * RDW) * 4)

__global__ __launch_bounds__(256, 1) void rnn_fused(
    const float* __restrict__ x,
    const float* __restrict__ w_ih0, const float* __restrict__ w_hh0,
    const float* __restrict__ b_ih0, const float* __restrict__ b_hh0,
    const float* __restrict__ w_ih1, const float* __restrict__ w_hh1,
    const float* __restrict__ b_ih1, const float* __restrict__ b_hh1,
    const float* __restrict__ w_fc, const float* __restrict__ b_fc,
    float* __restrict__ out,
    int* __restrict__ flags)
{
    extern __shared__ uint32_t smu[];
    uint32_t* Php = smu;                 // h_prev hi [16][RP]
    uint32_t* Plp = smu + 16 * RP;       // h_prev lo
    uint32_t* Ihp = smu + 2 * 16 * RP;   // input hi  [16][RP or XP]
    uint32_t* Ilp = smu + 3 * 16 * RP;   // input lo
    float*    Rd  = (float*)(smu + 4 * 16 * RP);  // [4*16][RDW]

    const int tid = threadIdx.x, lane = tid & 31, wp = tid >> 5;
    const int gid = lane >> 2, tg = lane & 3;
    const int wk = wp & 3, wj = wp >> 2;
    const int layer = blockIdx.x >> 6;
    const int inner = blockIdx.x & 63;
    const int bg = inner & 3, jg = inner >> 2;
    const int b0 = bg * 16, jbase = jg * 32;
    const int rb = tid >> 4, rjp = tid & 15;
    const bool L1 = (layer == 1);

    const float* whh = L1 ? w_hh1 : w_hh0;
    const float* wih = L1 ? w_ih1 : w_ih0;
    const float* bi  = L1 ? b_ih1 : b_ih0;
    const float* bh  = L1 ? b_hh1 : b_hh0;
    uint32_t* Ohw = L1 ? g_h1hi_b : g_h0hi_b;
    uint32_t* Olw = L1 ? g_h1lo_b : g_h0lo_b;

    const float bias0 = bi[jbase + 2 * rjp]     + bh[jbase + 2 * rjp];
    const float bias1 = bi[jbase + 2 * rjp + 1] + bh[jbase + 2 * rjp + 1];

    // ---- W_hh fragments -> registers ----
    uint32_t whf[8][2][2], wlf[8][2][2];
#pragma unroll
    for (int kc = 0; kc < 8; kc++) {
        int kp = wk * 64 + kc * 8 + tg;
#pragma unroll
        for (int nt = 0; nt < 2; nt++) {
            const float* wr = whh + (size_t)(jbase + wj * 16 + nt * 8 + gid) * HH;
            split2(*(const float2*)(wr + 2 * kp),     whf[kc][nt][0], wlf[kc][nt][0]);
            split2(*(const float2*)(wr + 2 * kp + 8), whf[kc][nt][1], wlf[kc][nt][1]);
        }
    }
    // ---- W_ih fragments ----
    uint32_t uhf[8][2][2], ulf[8][2][2];
    if (L1) {
#pragma unroll
        for (int kc = 0; kc < 8; kc++) {
            int kp = wk * 64 + kc * 8 + tg;
#pragma unroll
            for (int nt = 0; nt < 2; nt++) {
                const float* wr = wih + (size_t)(jbase + wj * 16 + nt * 8 + gid) * HH;
                split2(*(const float2*)(wr + 2 * kp),     uhf[kc][nt][0], ulf[kc][nt][0]);
                split2(*(const float2*)(wr + 2 * kp + 8), uhf[kc][nt][1], ulf[kc][nt][1]);
            }
        }
    } else {
#pragma unroll
        for (int kc = 0; kc < 4; kc++) {
            int kp = wk * 32 + kc * 8 + tg;
#pragma unroll
            for (int nt = 0; nt < 2; nt++) {
                const float* wr = wih + (size_t)(jbase + wj * 16 + nt * 8 + gid) * II;
                split2(*(const float2*)(wr + 2 * kp),     uhf[kc][nt][0], ulf[kc][nt][0]);
                split2(*(const float2*)(wr + 2 * kp + 8), uhf[kc][nt][1], ulf[kc][nt][1]);
            }
        }
    }

    for (int t = 0; t < SS; t++) {
        if (!L1) {
            // stage x_t (no dependency) while waiting; split inline
#pragma unroll
            for (int i = 0; i < 4; i++) {
                int f = tid + i * 256;
                int b = f >> 6, q = f & 63;
                float4 v = *(const float4*)(x + ((size_t)(b0 + b) * SS + t) * II + q * 4);
                uint32_t h0v, h1v, l0v, l1v; split4(v, h0v, h1v, l0v, l1v);
                *(uint2*)&Ihp[b * XP + q * 2] = make_uint2(h0v, h1v);
                *(uint2*)&Ilp[b * XP + q * 2] = make_uint2(l0v, l1v);
            }
            if (tid == 0 && t > 0) { while (ld_acq(flags + fidx(0, bg, t - 1)) < 16) { } }
            __syncthreads();
        } else {
            // parallel polls: tid0 -> own t-1, tid1 -> layer0 t
            if (tid < 2) {
                if (tid == 0) { if (t > 0) while (ld_acq(flags + fidx(1, bg, t - 1)) < 16) { } }
                else         { while (ld_acq(flags + fidx(0, bg, t)) < 16) { } }
            }
            __syncthreads();
            // stage input h0_t (blocked layout)
            {
                size_t bb = ((size_t)t * 4 + bg) * 4096;
#pragma unroll
                for (int i = 0; i < 4; i++) {
                    int f = tid + i * 256;
                    int b = f >> 6, in = f & 63;
                    int jgs = in >> 2, kq = in & 3;
                    size_t ga = bb + (size_t)jgs * 256 + b * 16 + kq * 4;
                    *(uint4*)&Ihp[b * RP + jgs * 16 + kq * 4] = __ldcg((const uint4*)(g_h0hi_b + ga));
                    *(uint4*)&Ilp[b * RP + jgs * 16 + kq * 4] = __ldcg((const uint4*)(g_h0lo_b + ga));
                }
            }
        }

        // stage h_prev (own layer, t-1, blocked layout)
        if (t > 0) {
            size_t bb = ((size_t)(t - 1) * 4 + bg) * 4096;
#pragma unroll
            for (int i = 0; i < 4; i++) {
                int f = tid + i * 256;
                int b = f >> 6, in = f & 63;
                int jgs = in >> 2, kq = in & 3;
                size_t ga = bb + (size_t)jgs * 256 + b * 16 + kq * 4;
                *(uint4*)&Php[b * RP + jgs * 16 + kq * 4] = __ldcg((const uint4*)(Ohw + ga));
                *(uint4*)&Plp[b * RP + jgs * 16 + kq * 4] = __ldcg((const uint4*)(Olw + ga));
            }
        } else {
#pragma unroll
            for (int i = 0; i < 4; i++) {
                int f = tid + i * 256;
                int b = f >> 6, q = f & 63;
                uint4 z = make_uint4(0, 0, 0, 0);
                *(uint4*)&Php[b * RP + q * 4] = z;
                *(uint4*)&Plp[b * RP + q * 4] = z;
            }
        }
        __syncthreads();

        float acc[2][4];
#pragma unroll
        for (int nt = 0; nt < 2; nt++)
#pragma unroll
            for (int c = 0; c < 4; c++) acc[nt][c] = 0.f;

        // ---- h_prev @ W_hh ----
#pragma unroll
        for (int kc = 0; kc < 8; kc++) {
            int kp = wk * 64 + kc * 8 + tg;
            int o0 = gid * RP + kp, o1 = (gid + 8) * RP + kp;
            uint32_t ahi[4] = { Php[o0], Php[o1], Php[o0 + 4], Php[o1 + 4] };
            uint32_t alo[4] = { Plp[o0], Plp[o1], Plp[o0 + 4], Plp[o1 + 4] };
#pragma unroll
            for (int nt = 0; nt < 2; nt++) {
                mma16(acc[nt], ahi, whf[kc][nt]);
                mma16(acc[nt], ahi, wlf[kc][nt]);
                mma16(acc[nt], alo, whf[kc][nt]);
            }
        }
        // ---- input @ W_ih ----
        if (L1) {
#pragma unroll
            for (int kc = 0; kc < 8; kc++) {
                int kp = wk * 64 + kc * 8 + tg;
                int o0 = gid * RP + kp, o1 = (gid + 8) * RP + kp;
                uint32_t ahi[4] = { Ihp[o0], Ihp[o1], Ihp[o0 + 4], Ihp[o1 + 4] };
                uint32_t alo[4] = { Ilp[o0], Ilp[o1], Ilp[o0 + 4], Ilp[o1 + 4] };
#pragma unroll
                for (int nt = 0; nt < 2; nt++) {
                    mma16(acc[nt], ahi, uhf[kc][nt]);
                    mma16(acc[nt], ahi, ulf[kc][nt]);
                    mma16(acc[nt], alo, uhf[kc][nt]);
                }
            }
        } else {
#pragma unroll
            for (int kc = 0; kc < 4; kc++) {
                int kp = wk * 32 + kc * 8 + tg;
                int o0 = gid * XP + kp, o1 = (gid + 8) * XP + kp;
                uint32_t ahi[4] = { Ihp[o0], Ihp[o1], Ihp[o0 + 4], Ihp[o1 + 4] };
                uint32_t alo[4] = { Ilp[o0], Ilp[o1], Ilp[o0 + 4], Ilp[o1 + 4] };
#pragma unroll
                for (int nt = 0; nt < 2; nt++) {
                    mma16(acc[nt], ahi, uhf[kc][nt]);
                    mma16(acc[nt], ahi, ulf[kc][nt]);
                    mma16(acc[nt], alo, uhf[kc][nt]);
                }
            }
        }

        // ---- partials -> Rd ----
#pragma unroll
        for (int nt = 0; nt < 2; nt++) {
            int col = wj * 16 + nt * 8 + tg * 2;
            int r0 = (wk * 16 + gid) * RDW + col;
            int r1 = (wk * 16 + gid + 8) * RDW + col;
            Rd[r0] = acc[nt][0]; Rd[r0 + 1] = acc[nt][1];
            Rd[r1] = acc[nt][2]; Rd[r1 + 1] = acc[nt][3];
        }
        __syncthreads();

        // ---- reduce, tanh, split-pack, blocked store ----
        {
            float s0 = 0.f, s1 = 0.f;
#pragma unroll
            for (int r = 0; r < 4; r++) {
                int o = (r * 16 + rb) * RDW + 2 * rjp;
                s0 += Rd[o]; s1 += Rd[o + 1];
            }
            float v0 = tanhf(bias0 + s0);
            float v1 = tanhf(bias1 + s1);
            uint32_t hp, lp; split2(make_float2(v0, v1), hp, lp);
            size_t oo = ((size_t)t * 4 + bg) * 4096 + (size_t)jg * 256 + rb * 16 + rjp;
            Ohw[oo] = hp;
            Olw[oo] = lp;
        }
        __syncthreads();
        if (tid == 0) red_rel(flags + fidx(layer, bg, t), 1);
    }

    // ---- FC head: L0 CTAs (idle now), one per batch ----
    if (!L1 && inner < BB) {
        const int b = inner;
        const int bgb = b >> 4, bi2 = b & 15;
        if (tid == 0) { while (ld_acq(flags + fidx(1, bgb, SS - 1)) < 16) { } }
        __syncthreads();
        size_t bb = ((size_t)(SS - 1) * 4 + bgb) * 4096 + bi2 * 16;
        for (int c = wp; c < CC; c += 8) {
            float accf = 0.f;
            for (int it = 0; it < 8; it++) {
                int kpg = lane + it * 32;             // global k-pair 0..255
                int jg2 = kpg >> 4, kpin = kpg & 15;
                size_t ga = bb + (size_t)jg2 * 256 + kpin;
                uint32_t vh = g_h1hi_b[ga], vl = g_h1lo_b[ga];
                float h0f = __uint_as_float(vh << 16) + __uint_as_float(vl << 16);
                float h1f = __uint_as_float(vh & 0xffff0000u) + __uint_as_float(vl & 0xffff0000u);
                accf += h0f * w_fc[c * HH + 2 * kpg] + h1f * w_fc[c * HH + 2 * kpg + 1];
            }
#pragma unroll
            for (int o = 16; o; o >>= 1) accf += __shfl_down_sync(0xffffffffu, accf, o);
            if (lane == 0) out[b * CC + c] = accf + b_fc[c];
        }
    }
}

// ---------------- launch ----------------
extern "C" void kernel_launch(void* const* d_in, const int* in_sizes, int n_in,
                              void* d_out, int out_size)
{
    const float* x     = (const float*)d_in[0];
    const float* w_ih0 = (const float*)d_in[1];
    const float* w_hh0 = (const float*)d_in[2];
    const float* b_ih0 = (const float*)d_in[3];
    const float* b_hh0 = (const float*)d_in[4];
    const float* w_ih1 = (const float*)d_in[5];
    const float* w_hh1 = (const float*)d_in[6];
    const float* b_ih1 = (const float*)d_in[7];
    const float* b_hh1 = (const float*)d_in[8];
    const float* w_fc  = (const float*)d_in[9];
    const float* b_fc  = (const float*)d_in[10];
    float* out = (float*)d_out;

    int* flags;
    cudaGetSymbolAddress((void**)&flags, g_flags);

    cudaFuncSetAttribute(rnn_fused,
                         cudaFuncAttributeMaxDynamicSharedMemorySize, FSMEM_BYTES);

    cudaMemsetAsync(flags, 0, 2 * 4 * SS * FS * sizeof(int));

    rnn_fused<<<128, 256, FSMEM_BYTES>>>(x,
                                         w_ih0, w_hh0, b_ih0, b_hh0,
                                         w_ih1, w_hh1, b_ih1, b_hh1,
                                         w_fc, b_fc, out, flags);
}

// round 12
// speedup vs baseline: 1.3365x; 1.0918x over previous
#include <cuda_runtime.h>
#include <cuda_bf16.h>
#include <cstdint>

#define BB 64
#define SS 512
#define II 256
#define HH 512
#define CC 10

// ---------------- scratch ----------------
__device__ __nv_bfloat16 g_h0hi[(size_t)BB * SS * HH];
__device__ __nv_bfloat16 g_h0lo[(size_t)BB * SS * HH];
__device__ __nv_bfloat16 g_h1hi[(size_t)BB * SS * HH];
__device__ __nv_bfloat16 g_h1lo[(size_t)BB * SS * HH];
__device__ int g_flags[2 * 4 * SS];        // [layer][bg][t] counters (to 16)

// ---------------- helpers ----------------
__device__ __forceinline__ uint32_t pk2(float e0, float e1) {
    uint32_t r; asm("cvt.rn.bf16x2.f32 %0, %1, %2;" : "=r"(r) : "f"(e1), "f"(e0)); return r;
}
__device__ __forceinline__ void split2(float2 v, uint32_t& h, uint32_t& l) {
    h = pk2(v.x, v.y);
    float f0 = __uint_as_float(h << 16);
    float f1 = __uint_as_float(h & 0xffff0000u);
    l = pk2(v.x - f0, v.y - f1);
}
__device__ __forceinline__ void split4(float4 v, uint32_t& h0, uint32_t& h1,
                                       uint32_t& l0, uint32_t& l1) {
    split2(make_float2(v.x, v.y), h0, l0);
    split2(make_float2(v.z, v.w), h1, l1);
}
__device__ __forceinline__ void mma16(float* d, const uint32_t* a, const uint32_t* b) {
    asm volatile("mma.sync.aligned.m16n8k16.row.col.f32.bf16.bf16.f32 "
                 "{%0,%1,%2,%3},{%4,%5,%6,%7},{%8,%9},{%0,%1,%2,%3};"
                 : "+f"(d[0]), "+f"(d[1]), "+f"(d[2]), "+f"(d[3])
                 : "r"(a[0]), "r"(a[1]), "r"(a[2]), "r"(a[3]), "r"(b[0]), "r"(b[1]));
}
__device__ __forceinline__ int ld_acq(const int* p) {
    int v; asm volatile("ld.acquire.gpu.global.s32 %0, [%1];" : "=r"(v) : "l"(p) : "memory");
    return v;
}
__device__ __forceinline__ void red_rel(int* p, int v) {
    asm volatile("red.release.gpu.global.add.s32 [%0], %1;" :: "l"(p), "r"(v) : "memory");
}

// ---------------- fused 2-layer RNN + FC head ----------------
// 128 CTAs (1/SM): layer = bx>>6; inner 64 = 4 bg(16 batches) x 16 jg(32 j).
// 8 warps = 4 k-parts(128k) x 2 j-halves(16j). All W fragments in registers.
// L1 schedule: dep-poll in the tail (inside the signal-visibility dead window);
// own-poll overlapped with the input stage at the head.
#define RP 260      // k-pair stride, 512-k stage (256 + 4)
#define XP 132      // k-pair stride, 256-k stage (128 + 4)
#define RDW 33      // reduce row stride
#define FSMEM_BYTES ((4 * 16 * RP + 64 * RDW) * 4)

__global__ __launch_bounds__(256, 1) void rnn_fused(
    const float* __restrict__ x,
    const float* __restrict__ w_ih0, const float* __restrict__ w_hh0,
    const float* __restrict__ b_ih0, const float* __restrict__ b_hh0,
    const float* __restrict__ w_ih1, const float* __restrict__ w_hh1,
    const float* __restrict__ b_ih1, const float* __restrict__ b_hh1,
    __nv_bfloat16* __restrict__ h0hi, __nv_bfloat16* __restrict__ h0lo,
    __nv_bfloat16* __restrict__ h1hi, __nv_bfloat16* __restrict__ h1lo,
    const float* __restrict__ w_fc, const float* __restrict__ b_fc,
    float* __restrict__ out,
    int* __restrict__ flags)
{
    extern __shared__ uint32_t smu[];
    uint32_t* Php = smu;                 // h_prev hi [16][RP]
    uint32_t* Plp = smu + 16 * RP;       // h_prev lo
    uint32_t* Ihp = smu + 2 * 16 * RP;   // input hi  [16][RP or XP]
    uint32_t* Ilp = smu + 3 * 16 * RP;   // input lo
    float*    Rd  = (float*)(smu + 4 * 16 * RP);  // [4*16][RDW]

    const int tid = threadIdx.x, lane = tid & 31, wp = tid >> 5;
    const int gid = lane >> 2, tg = lane & 3;
    const int wk = wp & 3, wj = wp >> 2;
    const int layer = blockIdx.x >> 6;
    const int inner = blockIdx.x & 63;
    const int bg = inner & 3, jg = inner >> 2;
    const int b0 = bg * 16, jbase = jg * 32;
    const int rb = tid >> 4, rjp = tid & 15;
    const bool L1 = (layer == 1);

    const float* whh = L1 ? w_hh1 : w_hh0;
    const float* wih = L1 ? w_ih1 : w_ih0;
    const float* bi  = L1 ? b_ih1 : b_ih0;
    const float* bh  = L1 ? b_hh1 : b_hh0;
    uint32_t* Ohw = (uint32_t*)(L1 ? h1hi : h0hi);
    uint32_t* Olw = (uint32_t*)(L1 ? h1lo : h0lo);
    const uint32_t* ihg = (const uint32_t*)h0hi;
    const uint32_t* ilg = (const uint32_t*)h0lo;
    int* fown = flags + layer * 4 * SS + bg * SS;
    int* fdep = flags + bg * SS;

    const float bias0 = bi[jbase + 2 * rjp]     + bh[jbase + 2 * rjp];
    const float bias1 = bi[jbase + 2 * rjp + 1] + bh[jbase + 2 * rjp + 1];

    // ---- W_hh fragments -> registers ----
    uint32_t whf[8][2][2], wlf[8][2][2];
#pragma unroll
    for (int kc = 0; kc < 8; kc++) {
        int kp = wk * 64 + kc * 8 + tg;
#pragma unroll
        for (int nt = 0; nt < 2; nt++) {
            const float* wr = whh + (size_t)(jbase + wj * 16 + nt * 8 + gid) * HH;
            split2(*(const float2*)(wr + 2 * kp),     whf[kc][nt][0], wlf[kc][nt][0]);
            split2(*(const float2*)(wr + 2 * kp + 8), whf[kc][nt][1], wlf[kc][nt][1]);
        }
    }
    // ---- W_ih fragments ----
    uint32_t uhf[8][2][2], ulf[8][2][2];
    if (L1) {
#pragma unroll
        for (int kc = 0; kc < 8; kc++) {
            int kp = wk * 64 + kc * 8 + tg;
#pragma unroll
            for (int nt = 0; nt < 2; nt++) {
                const float* wr = wih + (size_t)(jbase + wj * 16 + nt * 8 + gid) * HH;
                split2(*(const float2*)(wr + 2 * kp),     uhf[kc][nt][0], ulf[kc][nt][0]);
                split2(*(const float2*)(wr + 2 * kp + 8), uhf[kc][nt][1], ulf[kc][nt][1]);
            }
        }
    } else {
#pragma unroll
        for (int kc = 0; kc < 4; kc++) {
            int kp = wk * 32 + kc * 8 + tg;
#pragma unroll
            for (int nt = 0; nt < 2; nt++) {
                const float* wr = wih + (size_t)(jbase + wj * 16 + nt * 8 + gid) * II;
                split2(*(const float2*)(wr + 2 * kp),     uhf[kc][nt][0], ulf[kc][nt][0]);
                split2(*(const float2*)(wr + 2 * kp + 8), uhf[kc][nt][1], ulf[kc][nt][1]);
            }
        }
    }

    // ---- L1 prologue: confirm h0(0) availability (tail handles t>=1) ----
    if (L1) {
        if (tid == 0) { while (ld_acq(fdep + 0) < 16) { } }
        __syncthreads();
    }

    for (int t = 0; t < SS; t++) {
        if (!L1) {
            // stage x_t (no dependency) while tid0's own-poll spins
#pragma unroll
            for (int i = 0; i < 4; i++) {
                int f = tid + i * 256;
                int b = f >> 6, q = f & 63;
                float4 v = *(const float4*)(x + ((size_t)(b0 + b) * SS + t) * II + q * 4);
                uint32_t h0v, h1v, l0v, l1v; split4(v, h0v, h1v, l0v, l1v);
                *(uint2*)&Ihp[b * XP + q * 2] = make_uint2(h0v, h1v);
                *(uint2*)&Ilp[b * XP + q * 2] = make_uint2(l0v, l1v);
            }
            if (tid == 0 && t > 0) { while (ld_acq(fown + t - 1) < 16) { } }
            __syncthreads();
        } else {
            // own-poll (tid0) concurrent with input stage (dep confirmed in tail)
            if (tid == 0 && t > 0) { while (ld_acq(fown + t - 1) < 16) { } }
#pragma unroll
            for (int i = 0; i < 4; i++) {
                int f = tid + i * 256;
                int b = f >> 6, q = f & 63;
                size_t off = ((size_t)(b0 + b) * SS + t) * (HH / 2) + q * 4;
                *(uint4*)&Ihp[b * RP + q * 4] = __ldcg((const uint4*)(ihg + off));
                *(uint4*)&Ilp[b * RP + q * 4] = __ldcg((const uint4*)(ilg + off));
            }
            __syncthreads();
        }

        // stage h_prev (own layer, t-1) — gated by the sync above
        if (t > 0) {
#pragma unroll
            for (int i = 0; i < 4; i++) {
                int f = tid + i * 256;
                int b = f >> 6, q = f & 63;
                size_t off = ((size_t)(b0 + b) * SS + (t - 1)) * (HH / 2) + q * 4;
                *(uint4*)&Php[b * RP + q * 4] = __ldcg((const uint4*)(Ohw + off));
                *(uint4*)&Plp[b * RP + q * 4] = __ldcg((const uint4*)(Olw + off));
            }
        } else {
#pragma unroll
            for (int i = 0; i < 4; i++) {
                int f = tid + i * 256;
                int b = f >> 6, q = f & 63;
                uint4 z = make_uint4(0, 0, 0, 0);
                *(uint4*)&Php[b * RP + q * 4] = z;
                *(uint4*)&Plp[b * RP + q * 4] = z;
            }
        }
        __syncthreads();

        float acc[2][4];
#pragma unroll
        for (int nt = 0; nt < 2; nt++)
#pragma unroll
            for (int c = 0; c < 4; c++) acc[nt][c] = 0.f;

        // ---- h_prev @ W_hh ----
#pragma unroll
        for (int kc = 0; kc < 8; kc++) {
            int kp = wk * 64 + kc * 8 + tg;
            int o0 = gid * RP + kp, o1 = (gid + 8) * RP + kp;
            uint32_t ahi[4] = { Php[o0], Php[o1], Php[o0 + 4], Php[o1 + 4] };
            uint32_t alo[4] = { Plp[o0], Plp[o1], Plp[o0 + 4], Plp[o1 + 4] };
#pragma unroll
            for (int nt = 0; nt < 2; nt++) {
                mma16(acc[nt], ahi, whf[kc][nt]);
                mma16(acc[nt], ahi, wlf[kc][nt]);
                mma16(acc[nt], alo, whf[kc][nt]);
            }
        }
        // ---- input @ W_ih ----
        if (L1) {
#pragma unroll
            for (int kc = 0; kc < 8; kc++) {
                int kp = wk * 64 + kc * 8 + tg;
                int o0 = gid * RP + kp, o1 = (gid + 8) * RP + kp;
                uint32_t ahi[4] = { Ihp[o0], Ihp[o1], Ihp[o0 + 4], Ihp[o1 + 4] };
                uint32_t alo[4] = { Ilp[o0], Ilp[o1], Ilp[o0 + 4], Ilp[o1 + 4] };
#pragma unroll
                for (int nt = 0; nt < 2; nt++) {
                    mma16(acc[nt], ahi, uhf[kc][nt]);
                    mma16(acc[nt], ahi, ulf[kc][nt]);
                    mma16(acc[nt], alo, uhf[kc][nt]);
                }
            }
        } else {
#pragma unroll
            for (int kc = 0; kc < 4; kc++) {
                int kp = wk * 32 + kc * 8 + tg;
                int o0 = gid * XP + kp, o1 = (gid + 8) * XP + kp;
                uint32_t ahi[4] = { Ihp[o0], Ihp[o1], Ihp[o0 + 4], Ihp[o1 + 4] };
                uint32_t alo[4] = { Ilp[o0], Ilp[o1], Ilp[o0 + 4], Ilp[o1 + 4] };
#pragma unroll
                for (int nt = 0; nt < 2; nt++) {
                    mma16(acc[nt], ahi, uhf[kc][nt]);
                    mma16(acc[nt], ahi, ulf[kc][nt]);
                    mma16(acc[nt], alo, uhf[kc][nt]);
                }
            }
        }

        // ---- partials -> Rd ----
#pragma unroll
        for (int nt = 0; nt < 2; nt++) {
            int col = wj * 16 + nt * 8 + tg * 2;
            int r0 = (wk * 16 + gid) * RDW + col;
            int r1 = (wk * 16 + gid + 8) * RDW + col;
            Rd[r0] = acc[nt][0]; Rd[r0 + 1] = acc[nt][1];
            Rd[r1] = acc[nt][2]; Rd[r1 + 1] = acc[nt][3];
        }
        __syncthreads();

        // ---- reduce, tanh, split-pack-store ----
        {
            float s0 = 0.f, s1 = 0.f;
#pragma unroll
            for (int r = 0; r < 4; r++) {
                int o = (r * 16 + rb) * RDW + 2 * rjp;
                s0 += Rd[o]; s1 += Rd[o + 1];
            }
            float v0 = tanhf(bias0 + s0);
            float v1 = tanhf(bias1 + s1);
            uint32_t hp, lp; split2(make_float2(v0, v1), hp, lp);
            size_t oo = ((size_t)(b0 + rb) * SS + t) * (HH / 2) + (jbase >> 1) + rjp;
            Ohw[oo] = hp;
            Olw[oo] = lp;
        }
        __syncthreads();
        if (tid == 0) red_rel(fown + t, 1);

        // ---- L1 tail: dep-poll for next input inside the visibility window ----
        if (L1 && t + 1 < SS) {
            if (tid == 0) { while (ld_acq(fdep + t + 1) < 16) { } }
            __syncthreads();
        }
    }

    // ---- FC head: L0 CTAs (idle now), one per batch ----
    if (!L1 && inner < BB) {
        const int b = inner;
        if (tid == 0) {
            const int* f1 = flags + 4 * SS + (b >> 4) * SS + (SS - 1);
            while (ld_acq(f1) < 16) { }
        }
        __syncthreads();
        const __nv_bfloat16* hb = h1hi + ((size_t)b * SS + (SS - 1)) * HH;
        const __nv_bfloat16* lb = h1lo + ((size_t)b * SS + (SS - 1)) * HH;
        for (int c = wp; c < CC; c += 8) {
            float accf = 0.f;
            for (int j = lane; j < HH; j += 32) {
                float h = __bfloat162float(hb[j]) + __bfloat162float(lb[j]);
                accf += h * w_fc[c * HH + j];
            }
#pragma unroll
            for (int o = 16; o; o >>= 1) accf += __shfl_down_sync(0xffffffffu, accf, o);
            if (lane == 0) out[b * CC + c] = accf + b_fc[c];
        }
    }
}

// ---------------- launch ----------------
extern "C" void kernel_launch(void* const* d_in, const int* in_sizes, int n_in,
                              void* d_out, int out_size)
{
    const float* x     = (const float*)d_in[0];
    const float* w_ih0 = (const float*)d_in[1];
    const float* w_hh0 = (const float*)d_in[2];
    const float* b_ih0 = (const float*)d_in[3];
    const float* b_hh0 = (const float*)d_in[4];
    const float* w_ih1 = (const float*)d_in[5];
    const float* w_hh1 = (const float*)d_in[6];
    const float* b_ih1 = (const float*)d_in[7];
    const float* b_hh1 = (const float*)d_in[8];
    const float* w_fc  = (const float*)d_in[9];
    const float* b_fc  = (const float*)d_in[10];
    float* out = (float*)d_out;

    __nv_bfloat16 *h0hi, *h0lo, *h1hi, *h1lo;
    int* flags;
    cudaGetSymbolAddress((void**)&h0hi, g_h0hi);
    cudaGetSymbolAddress((void**)&h0lo, g_h0lo);
    cudaGetSymbolAddress((void**)&h1hi, g_h1hi);
    cudaGetSymbolAddress((void**)&h1lo, g_h1lo);
    cudaGetSymbolAddress((void**)&flags, g_flags);

    cudaFuncSetAttribute(rnn_fused,
                         cudaFuncAttributeMaxDynamicSharedMemorySize, FSMEM_BYTES);

    cudaMemsetAsync(flags, 0, 2 * 4 * SS * sizeof(int));

    rnn_fused<<<128, 256, FSMEM_BYTES>>>(x,
                                         w_ih0, w_hh0, b_ih0, b_hh0,
                                         w_ih1, w_hh1, b_ih1, b_hh1,
                                         h0hi, h0lo, h1hi, h1lo,
                                         w_fc, b_fc, out, flags);
}

// round 14
// speedup vs baseline: 1.3894x; 1.0396x over previous
#include <cuda_runtime.h>
#include <cuda_bf16.h>
#include <cstdint>

#define BB 64
#define SS 512
#define II 256
#define HH 512
#define CC 10

// ---------------- scratch ----------------
__device__ __nv_bfloat16 g_h0hi[(size_t)BB * SS * HH];
__device__ __nv_bfloat16 g_h0lo[(size_t)BB * SS * HH];
__device__ __nv_bfloat16 g_h1hi[(size_t)BB * SS * HH];
__device__ __nv_bfloat16 g_h1lo[(size_t)BB * SS * HH];
__device__ int g_flags[2 * 4 * SS];        // [layer][bg][t] counters (to 16)

// ---------------- helpers ----------------
__device__ __forceinline__ uint32_t pk2(float e0, float e1) {
    uint32_t r; asm("cvt.rn.bf16x2.f32 %0, %1, %2;" : "=r"(r) : "f"(e1), "f"(e0)); return r;
}
__device__ __forceinline__ void split2(float2 v, uint32_t& h, uint32_t& l) {
    h = pk2(v.x, v.y);
    float f0 = __uint_as_float(h << 16);
    float f1 = __uint_as_float(h & 0xffff0000u);
    l = pk2(v.x - f0, v.y - f1);
}
__device__ __forceinline__ void split4(float4 v, uint32_t& h0, uint32_t& h1,
                                       uint32_t& l0, uint32_t& l1) {
    split2(make_float2(v.x, v.y), h0, l0);
    split2(make_float2(v.z, v.w), h1, l1);
}
__device__ __forceinline__ void mma16(float* d, const uint32_t* a, const uint32_t* b) {
    asm volatile("mma.sync.aligned.m16n8k16.row.col.f32.bf16.bf16.f32 "
                 "{%0,%1,%2,%3},{%4,%5,%6,%7},{%8,%9},{%0,%1,%2,%3};"
                 : "+f"(d[0]), "+f"(d[1]), "+f"(d[2]), "+f"(d[3])
                 : "r"(a[0]), "r"(a[1]), "r"(a[2]), "r"(a[3]), "r"(b[0]), "r"(b[1]));
}
__device__ __forceinline__ int ld_acq(const int* p) {
    int v; asm volatile("ld.acquire.gpu.global.s32 %0, [%1];" : "=r"(v) : "l"(p) : "memory");
    return v;
}
__device__ __forceinline__ void red_rel(int* p, int v) {
    asm volatile("red.release.gpu.global.add.s32 [%0], %1;" :: "l"(p), "r"(v) : "memory");
}
__device__ __forceinline__ void cpa16(void* smem, const void* g) {
    uint32_t s = (uint32_t)__cvta_generic_to_shared(smem);
    asm volatile("cp.async.cg.shared.global [%0], [%1], 16;" :: "r"(s), "l"(g) : "memory");
}
__device__ __forceinline__ void cpa_commit() {
    asm volatile("cp.async.commit_group;" ::: "memory");
}
template<int N> __device__ __forceinline__ void cpa_wait() {
    asm volatile("cp.async.wait_group %0;" :: "n"(N) : "memory");
}

// ---------------- fused 2-layer RNN + FC head ----------------
// 128 CTAs (1/SM): layer = bx>>6; inner 64 = 4 bg(16 batches) x 16 jg(32 j).
// 8 warps = 4 k-parts(128k) x 2 j-halves(16j). All W fragments in registers.
// Step order: [poll||input-stage] -> cpa(h_prev) -> ih-MMA (covers flight)
//             -> wait -> hh-MMA -> reduce -> signal -> L1 tail dep-poll.
#define RP 260      // k-pair stride, 512-k stage (256 + 4)
#define XP 132      // k-pair stride, 256-k stage (128 + 4)
#define RDW 33      // reduce row stride
#define FSMEM_BYTES ((4 * 16 * RP + 64 * RDW) * 4)

__global__ __launch_bounds__(256, 1) void rnn_fused(
    const float* __restrict__ x,
    const float* __restrict__ w_ih0, const float* __restrict__ w_hh0,
    const float* __restrict__ b_ih0, const float* __restrict__ b_hh0,
    const float* __restrict__ w_ih1, const float* __restrict__ w_hh1,
    const float* __restrict__ b_ih1, const float* __restrict__ b_hh1,
    __nv_bfloat16* __restrict__ h0hi, __nv_bfloat16* __restrict__ h0lo,
    __nv_bfloat16* __restrict__ h1hi, __nv_bfloat16* __restrict__ h1lo,
    const float* __restrict__ w_fc, const float* __restrict__ b_fc,
    float* __restrict__ out,
    int* __restrict__ flags)
{
    extern __shared__ uint32_t smu[];
    uint32_t* Php = smu;                 // h_prev hi [16][RP]
    uint32_t* Plp = smu + 16 * RP;       // h_prev lo
    uint32_t* Ihp = smu + 2 * 16 * RP;   // input hi  [16][RP or XP]
    uint32_t* Ilp = smu + 3 * 16 * RP;   // input lo
    float*    Rd  = (float*)(smu + 4 * 16 * RP);  // [4*16][RDW]

    const int tid = threadIdx.x, lane = tid & 31, wp = tid >> 5;
    const int gid = lane >> 2, tg = lane & 3;
    const int wk = wp & 3, wj = wp >> 2;
    const int layer = blockIdx.x >> 6;
    const int inner = blockIdx.x & 63;
    const int bg = inner & 3, jg = inner >> 2;
    const int b0 = bg * 16, jbase = jg * 32;
    const int rb = tid >> 4, rjp = tid & 15;
    const bool L1 = (layer == 1);

    const float* whh = L1 ? w_hh1 : w_hh0;
    const float* wih = L1 ? w_ih1 : w_ih0;
    const float* bi  = L1 ? b_ih1 : b_ih0;
    const float* bh  = L1 ? b_hh1 : b_hh0;
    uint32_t* Ohw = (uint32_t*)(L1 ? h1hi : h0hi);
    uint32_t* Olw = (uint32_t*)(L1 ? h1lo : h0lo);
    const uint32_t* ihg = (const uint32_t*)h0hi;
    const uint32_t* ilg = (const uint32_t*)h0lo;
    int* fown = flags + layer * 4 * SS + bg * SS;
    int* fdep = flags + bg * SS;

    const float bias0 = bi[jbase + 2 * rjp]     + bh[jbase + 2 * rjp];
    const float bias1 = bi[jbase + 2 * rjp + 1] + bh[jbase + 2 * rjp + 1];

    // ---- W_hh fragments -> registers ----
    uint32_t whf[8][2][2], wlf[8][2][2];
#pragma unroll
    for (int kc = 0; kc < 8; kc++) {
        int kp = wk * 64 + kc * 8 + tg;
#pragma unroll
        for (int nt = 0; nt < 2; nt++) {
            const float* wr = whh + (size_t)(jbase + wj * 16 + nt * 8 + gid) * HH;
            split2(*(const float2*)(wr + 2 * kp),     whf[kc][nt][0], wlf[kc][nt][0]);
            split2(*(const float2*)(wr + 2 * kp + 8), whf[kc][nt][1], wlf[kc][nt][1]);
        }
    }
    // ---- W_ih fragments ----
    uint32_t uhf[8][2][2], ulf[8][2][2];
    if (L1) {
#pragma unroll
        for (int kc = 0; kc < 8; kc++) {
            int kp = wk * 64 + kc * 8 + tg;
#pragma unroll
            for (int nt = 0; nt < 2; nt++) {
                const float* wr = wih + (size_t)(jbase + wj * 16 + nt * 8 + gid) * HH;
                split2(*(const float2*)(wr + 2 * kp),     uhf[kc][nt][0], ulf[kc][nt][0]);
                split2(*(const float2*)(wr + 2 * kp + 8), uhf[kc][nt][1], ulf[kc][nt][1]);
            }
        }
    } else {
#pragma unroll
        for (int kc = 0; kc < 4; kc++) {
            int kp = wk * 32 + kc * 8 + tg;
#pragma unroll
            for (int nt = 0; nt < 2; nt++) {
                const float* wr = wih + (size_t)(jbase + wj * 16 + nt * 8 + gid) * II;
                split2(*(const float2*)(wr + 2 * kp),     uhf[kc][nt][0], ulf[kc][nt][0]);
                split2(*(const float2*)(wr + 2 * kp + 8), uhf[kc][nt][1], ulf[kc][nt][1]);
            }
        }
    }

    // ---- L1 prologue: confirm h0(0) availability (tail handles t>=1) ----
    if (L1) {
        if (tid == 0) { while (ld_acq(fdep + 0) < 16) { } }
        __syncthreads();
    }

    for (int t = 0; t < SS; t++) {
        if (!L1) {
            // stage x_t (no dependency) while tid0's own-poll spins
#pragma unroll
            for (int i = 0; i < 4; i++) {
                int f = tid + i * 256;
                int b = f >> 6, q = f & 63;
                float4 v = *(const float4*)(x + ((size_t)(b0 + b) * SS + t) * II + q * 4);
                uint32_t h0v, h1v, l0v, l1v; split4(v, h0v, h1v, l0v, l1v);
                *(uint2*)&Ihp[b * XP + q * 2] = make_uint2(h0v, h1v);
                *(uint2*)&Ilp[b * XP + q * 2] = make_uint2(l0v, l1v);
            }
            if (tid == 0 && t > 0) { while (ld_acq(fown + t - 1) < 16) { } }
            __syncthreads();
        } else {
            // own-poll (tid0) concurrent with input stage (dep confirmed in tail)
            if (tid == 0 && t > 0) { while (ld_acq(fown + t - 1) < 16) { } }
#pragma unroll
            for (int i = 0; i < 4; i++) {
                int f = tid + i * 256;
                int b = f >> 6, q = f & 63;
                size_t off = ((size_t)(b0 + b) * SS + t) * (HH / 2) + q * 4;
                *(uint4*)&Ihp[b * RP + q * 4] = __ldcg((const uint4*)(ihg + off));
                *(uint4*)&Ilp[b * RP + q * 4] = __ldcg((const uint4*)(ilg + off));
            }
            __syncthreads();
        }

        // ---- h_prev stage via cp.async (flight covered by ih-MMA below) ----
        if (t > 0) {
#pragma unroll
            for (int i = 0; i < 4; i++) {
                int f = tid + i * 256;
                int b = f >> 6, q = f & 63;
                size_t off = ((size_t)(b0 + b) * SS + (t - 1)) * (HH / 2) + q * 4;
                cpa16(&Php[b * RP + q * 4], Ohw + off);
                cpa16(&Plp[b * RP + q * 4], Olw + off);
            }
        } else {
#pragma unroll
            for (int i = 0; i < 4; i++) {
                int f = tid + i * 256;
                int b = f >> 6, q = f & 63;
                uint4 z = make_uint4(0, 0, 0, 0);
                *(uint4*)&Php[b * RP + q * 4] = z;
                *(uint4*)&Plp[b * RP + q * 4] = z;
            }
        }
        cpa_commit();

        float acc[2][4];
#pragma unroll
        for (int nt = 0; nt < 2; nt++)
#pragma unroll
            for (int c = 0; c < 4; c++) acc[nt][c] = 0.f;

        // ---- input @ W_ih (h_prev in flight) ----
        if (L1) {
#pragma unroll
            for (int kc = 0; kc < 8; kc++) {
                int kp = wk * 64 + kc * 8 + tg;
                int o0 = gid * RP + kp, o1 = (gid + 8) * RP + kp;
                uint32_t ahi[4] = { Ihp[o0], Ihp[o1], Ihp[o0 + 4], Ihp[o1 + 4] };
                uint32_t alo[4] = { Ilp[o0], Ilp[o1], Ilp[o0 + 4], Ilp[o1 + 4] };
#pragma unroll
                for (int nt = 0; nt < 2; nt++) {
                    mma16(acc[nt], ahi, uhf[kc][nt]);
                    mma16(acc[nt], ahi, ulf[kc][nt]);
                    mma16(acc[nt], alo, uhf[kc][nt]);
                }
            }
        } else {
#pragma unroll
            for (int kc = 0; kc < 4; kc++) {
                int kp = wk * 32 + kc * 8 + tg;
                int o0 = gid * XP + kp, o1 = (gid + 8) * XP + kp;
                uint32_t ahi[4] = { Ihp[o0], Ihp[o1], Ihp[o0 + 4], Ihp[o1 + 4] };
                uint32_t alo[4] = { Ilp[o0], Ilp[o1], Ilp[o0 + 4], Ilp[o1 + 4] };
#pragma unroll
                for (int nt = 0; nt < 2; nt++) {
                    mma16(acc[nt], ahi, uhf[kc][nt]);
                    mma16(acc[nt], ahi, ulf[kc][nt]);
                    mma16(acc[nt], alo, uhf[kc][nt]);
                }
            }
        }

        cpa_wait<0>();
        __syncthreads();

        // ---- h_prev @ W_hh ----
#pragma unroll
        for (int kc = 0; kc < 8; kc++) {
            int kp = wk * 64 + kc * 8 + tg;
            int o0 = gid * RP + kp, o1 = (gid + 8) * RP + kp;
            uint32_t ahi[4] = { Php[o0], Php[o1], Php[o0 + 4], Php[o1 + 4] };
            uint32_t alo[4] = { Plp[o0], Plp[o1], Plp[o0 + 4], Plp[o1 + 4] };
#pragma unroll
            for (int nt = 0; nt < 2; nt++) {
                mma16(acc[nt], ahi, whf[kc][nt]);
                mma16(acc[nt], ahi, wlf[kc][nt]);
                mma16(acc[nt], alo, whf[kc][nt]);
            }
        }

        // ---- partials -> Rd ----
#pragma unroll
        for (int nt = 0; nt < 2; nt++) {
            int col = wj * 16 + nt * 8 + tg * 2;
            int r0 = (wk * 16 + gid) * RDW + col;
            int r1 = (wk * 16 + gid + 8) * RDW + col;
            Rd[r0] = acc[nt][0]; Rd[r0 + 1] = acc[nt][1];
            Rd[r1] = acc[nt][2]; Rd[r1 + 1] = acc[nt][3];
        }
        __syncthreads();

        // ---- reduce, tanh, split-pack-store ----
        {
            float s0 = 0.f, s1 = 0.f;
#pragma unroll
            for (int r = 0; r < 4; r++) {
                int o = (r * 16 + rb) * RDW + 2 * rjp;
                s0 += Rd[o]; s1 += Rd[o + 1];
            }
            float v0 = tanhf(bias0 + s0);
            float v1 = tanhf(bias1 + s1);
            uint32_t hp, lp; split2(make_float2(v0, v1), hp, lp);
            size_t oo = ((size_t)(b0 + rb) * SS + t) * (HH / 2) + (jbase >> 1) + rjp;
            Ohw[oo] = hp;
            Olw[oo] = lp;
        }
        __syncthreads();
        if (tid == 0) red_rel(fown + t, 1);

        // ---- L1 tail: dep-poll for next input inside the visibility window ----
        if (L1 && t + 1 < SS) {
            if (tid == 0) { while (ld_acq(fdep + t + 1) < 16) { } }
            __syncthreads();
        }
    }

    // ---- FC head: L0 CTAs (idle now), one per batch ----
    if (!L1 && inner < BB) {
        const int b = inner;
        if (tid == 0) {
            const int* f1 = flags + 4 * SS + (b >> 4) * SS + (SS - 1);
            while (ld_acq(f1) < 16) { }
        }
        __syncthreads();
        const __nv_bfloat16* hb = h1hi + ((size_t)b * SS + (SS - 1)) * HH;
        const __nv_bfloat16* lb = h1lo + ((size_t)b * SS + (SS - 1)) * HH;
        for (int c = wp; c < CC; c += 8) {
            float accf = 0.f;
            for (int j = lane; j < HH; j += 32) {
                float h = __bfloat162float(hb[j]) + __bfloat162float(lb[j]);
                accf += h * w_fc[c * HH + j];
            }
#pragma unroll
            for (int o = 16; o; o >>= 1) accf += __shfl_down_sync(0xffffffffu, accf, o);
            if (lane == 0) out[b * CC + c] = accf + b_fc[c];
        }
    }
}

// ---------------- launch ----------------
extern "C" void kernel_launch(void* const* d_in, const int* in_sizes, int n_in,
                              void* d_out, int out_size)
{
    const float* x     = (const float*)d_in[0];
    const float* w_ih0 = (const float*)d_in[1];
    const float* w_hh0 = (const float*)d_in[2];
    const float* b_ih0 = (const float*)d_in[3];
    const float* b_hh0 = (const float*)d_in[4];
    const float* w_ih1 = (const float*)d_in[5];
    const float* w_hh1 = (const float*)d_in[6];
    const float* b_ih1 = (const float*)d_in[7];
    const float* b_hh1 = (const float*)d_in[8];
    const float* w_fc  = (const float*)d_in[9];
    const float* b_fc  = (const float*)d_in[10];
    float* out = (float*)d_out;

    __nv_bfloat16 *h0hi, *h0lo, *h1hi, *h1lo;
    int* flags;
    cudaGetSymbolAddress((void**)&h0hi, g_h0hi);
    cudaGetSymbolAddress((void**)&h0lo, g_h0lo);
    cudaGetSymbolAddress((void**)&h1hi, g_h1hi);
    cudaGetSymbolAddress((void**)&h1lo, g_h1lo);
    cudaGetSymbolAddress((void**)&flags, g_flags);

    cudaFuncSetAttribute(rnn_fused,
                         cudaFuncAttributeMaxDynamicSharedMemorySize, FSMEM_BYTES);

    cudaMemsetAsync(flags, 0, 2 * 4 * SS * sizeof(int));

    rnn_fused<<<128, 256, FSMEM_BYTES>>>(x,
                                         w_ih0, w_hh0, b_ih0, b_hh0,
                                         w_ih1, w_hh1, b_ih1, b_hh1,
                                         h0hi, h0lo, h1hi, h1lo,
                                         w_fc, b_fc, out, flags);
}